// round 15
// baseline (speedup 1.0000x reference)
#include <cuda_runtime.h>
#include <cuda_fp16.h>
#include <cstdint>

#define NNODE 100000
#define NEDGE 1600000
#define ETOT  1700000   // NEDGE + NNODE self loops
#define NBLK  98        // ceil(NNODE / 1024) for the scan
#define BM    128       // rows per GEMM CTA
#define KC    64        // K chunk (2 chunks of 64)
#define XSTR  68        // xs chunk row stride (floats): 16B-aligned, bank+4/row

// ---------------- scratch (device globals; no allocation allowed) ----------
__device__ __half g_h [NNODE * 128];   // fp16: halves the agg gather traffic
__device__ float g_o  [NNODE * 128];
__device__ float g_als[NNODE * 2];
__device__ float g_ald[NNODE * 2];
__device__ int   g_cnt [NNODE];        // statically zero; re-zeroed by scan1
__device__ int   g_ptr [NNODE + 1];
__device__ int   g_bsum[128];
__device__ int   g_ssrc[ETOT];

// ---------------- f32x2 packed-FMA helpers (sm_103a) ------------------------
typedef unsigned long long u64;
__device__ __forceinline__ u64 splat2(float v) {
    u64 r; asm("mov.b64 %0, {%1, %1};" : "=l"(r) : "f"(v)); return r;
}
__device__ __forceinline__ void ffma2(u64& d, u64 a, u64 b) {
    asm("fma.rn.f32x2 %0, %1, %2, %0;" : "+l"(d) : "l"(a), "l"(b));
}
__device__ __forceinline__ float2 unpack2(u64 v) {
    float2 f; asm("mov.b64 {%0, %1}, %2;" : "=f"(f.x), "=f"(f.y) : "l"(v)); return f;
}

// ---------------- CSR build: hist -> scan -> scatter ------------------------
__global__ void hist_kernel(const int* __restrict__ ei) {
    int i = blockIdx.x * blockDim.x + threadIdx.x;
    if (i >= ETOT) return;
    int d = (i < NEDGE) ? ei[NEDGE + i] : (i - NEDGE);
    atomicAdd(&g_cnt[d], 1);
}

// Reads g_cnt, writes per-block-exclusive offsets into g_ptr, block totals to
// g_bsum, and ZEROES g_cnt for the next graph replay (launch is idempotent).
__global__ __launch_bounds__(256) void scan1_kernel() {
    __shared__ int warp_tot[8];
    __shared__ int wofs[8];
    int b = blockIdx.x, t = threadIdx.x;
    int gi = b * 1024 + t * 4;
    int c0 = (gi     < NNODE) ? g_cnt[gi]     : 0;
    int c1 = (gi + 1 < NNODE) ? g_cnt[gi + 1] : 0;
    int c2 = (gi + 2 < NNODE) ? g_cnt[gi + 2] : 0;
    int c3 = (gi + 3 < NNODE) ? g_cnt[gi + 3] : 0;
    if (gi     < NNODE) g_cnt[gi]     = 0;
    if (gi + 1 < NNODE) g_cnt[gi + 1] = 0;
    if (gi + 2 < NNODE) g_cnt[gi + 2] = 0;
    if (gi + 3 < NNODE) g_cnt[gi + 3] = 0;
    int ts = c0 + c1 + c2 + c3;
    int lane = t & 31, wid = t >> 5;
    int inc = ts;
    #pragma unroll
    for (int o = 1; o < 32; o <<= 1) {
        int v = __shfl_up_sync(0xffffffffu, inc, o);
        if (lane >= o) inc += v;
    }
    if (lane == 31) warp_tot[wid] = inc;
    __syncthreads();
    if (t == 0) {
        int acc = 0;
        #pragma unroll
        for (int w = 0; w < 8; w++) { wofs[w] = acc; acc += warp_tot[w]; }
        g_bsum[b] = acc;
    }
    __syncthreads();
    int base = wofs[wid] + inc - ts;
    if (gi     < NNODE) g_ptr[gi]     = base;
    if (gi + 1 < NNODE) g_ptr[gi + 1] = base + c0;
    if (gi + 2 < NNODE) g_ptr[gi + 2] = base + c0 + c1;
    if (gi + 3 < NNODE) g_ptr[gi + 3] = base + c0 + c1 + c2;
}

// Fused scan2+scan3: every block redoes the tiny 128-wide scan of g_bsum in
// smem (7 rounds), then adds its chunk's exclusive prefix to g_ptr.
__global__ __launch_bounds__(256) void scan23_kernel() {
    __shared__ int s[128];
    int t = threadIdx.x;
    if (t < 128) s[t] = (t < NBLK) ? g_bsum[t] : 0;
    __syncthreads();
    #pragma unroll
    for (int o = 1; o < 128; o <<= 1) {
        int u = 0;
        if (t < 128 && t >= o) u = s[t - o];
        __syncthreads();
        if (t < 128) s[t] += u;
        __syncthreads();
    }
    int i = blockIdx.x * 256 + t;
    int bidx = blockIdx.x >> 2;                  // 4 blocks per 1024-chunk
    int add = (bidx == 0) ? 0 : s[bidx - 1];     // exclusive chunk prefix
    if (i < NNODE) g_ptr[i] += add;
}

// scatter mutates g_ptr: atomicAdd turns exclusive start into inclusive end.
// After this kernel: g_ptr[d] = end(d); agg reads [ptr[d-1], ptr[d]), ptr[-1]=0.
// Replay-safe: scan1 rewrites g_ptr from scratch every launch.
__global__ void scatter_kernel(const int* __restrict__ ei) {
    int i = blockIdx.x * blockDim.x + threadIdx.x;
    if (i >= ETOT) return;
    int s, d;
    if (i < NEDGE) { s = ei[i]; d = ei[NEDGE + i]; }
    else           { s = d = i - NEDGE; }
    int pos = atomicAdd(&g_ptr[d], 1);
    g_ssrc[pos] = s;
}

// ---------------- fused GEMM + attention-logit epilogue (FFMA2) -------------
// h = act(X) @ W  (act = relu(x + bias) if TRANS), writes g_h (fp16), g_als,
// g_ald (fp32, from fp32 accumulators). BM=128, 8x8 thread tile, K chunked
// 2x64 (smem ~69KB -> 2 CTAs/SM). FMA pipe is the binder.
template <int NOUT, bool TRANS>
__global__ __launch_bounds__(256, 2) void gemm_al(
    const float* __restrict__ X, const float* __restrict__ W,
    const float* __restrict__ asrc, const float* __restrict__ adst,
    const float* __restrict__ bias)
{
    constexpr int H   = NOUT / 64;
    constexpr int TX  = NOUT / 8;    // 16 (NOUT=128) or 8 (NOUT=64)
    constexpr int TY  = 256 / TX;    // 16 or 32
    constexpr int RPT = BM / TY;     // 8 or 4 rows per thread

    extern __shared__ float sm[];
    float* xs  = sm;                    // BM x XSTR (one 64-k chunk)
    float* ws  = sm + BM * XSTR;        // KC x NOUT (half-interleaved chunk)
    float* as_ = ws + KC * NOUT;        // NOUT
    float* ad_ = as_ + NOUT;            // NOUT
    float* bs  = ad_ + NOUT;            // 128

    const int tid = threadIdx.x;
    if (tid < NOUT) { as_[tid] = asrc[tid]; ad_[tid] = adst[tid]; }
    if (TRANS && tid < 128) bs[tid] = bias[tid];

    const int n0 = blockIdx.x * BM;
    const int ty = tid / TX, tx = tid % TX;

    u64 acc[RPT][4];
    #pragma unroll
    for (int j = 0; j < RPT; j++)
        #pragma unroll
        for (int i = 0; i < 4; i++) acc[j][i] = 0ull;

    const float4* W4  = (const float4*)W;
    float4*       ws4 = (float4*)ws;

    #pragma unroll
    for (int c = 0; c < 128 / KC; c++) {
        __syncthreads();   // protect smem reuse across chunks (and meta on c=0)

        // W chunk -> smem, half-interleaved within each k row
        #pragma unroll
        for (int i = tid; i < KC * NOUT / 4; i += 256) {
            int kk = i / (NOUT / 4);
            int c4 = i % (NOUT / 4);
            ws4[kk * (NOUT / 4) + (c4 & 1) * (NOUT / 8) + (c4 >> 1)] =
                W4[(size_t)(c * KC + kk) * (NOUT / 4) + c4];
        }

        // X chunk -> smem with fused relu(x + b)
        #pragma unroll
        for (int i = tid; i < BM * (KC / 4); i += 256) {
            int r   = i >> 4;              // KC/4 = 16
            int k4c = i & 15;
            int k4  = c * (KC / 4) + k4c;
            int n   = n0 + r;
            float4 v = make_float4(0.f, 0.f, 0.f, 0.f);
            if (n < NNODE) {
                v = ((const float4*)X)[(size_t)n * 32 + k4];
                if (TRANS) {
                    v.x = fmaxf(v.x + bs[k4 * 4 + 0], 0.f);
                    v.y = fmaxf(v.y + bs[k4 * 4 + 1], 0.f);
                    v.z = fmaxf(v.z + bs[k4 * 4 + 2], 0.f);
                    v.w = fmaxf(v.w + bs[k4 * 4 + 3], 0.f);
                }
            }
            *(float4*)(xs + r * XSTR + k4c * 4) = v;
        }
        __syncthreads();

        #pragma unroll 2
        for (int k0 = 0; k0 < KC; k0 += 4) {
            float a_[RPT][4];
            #pragma unroll
            for (int j = 0; j < RPT; j++) {
                float4 t = *(const float4*)(xs + (ty + TY * j) * XSTR + k0);
                a_[j][0] = t.x; a_[j][1] = t.y; a_[j][2] = t.z; a_[j][3] = t.w;
            }
            #pragma unroll
            for (int dk = 0; dk < 4; dk++) {
                const float* wp = ws + (k0 + dk) * NOUT + tx * 4;
                ulonglong2 bA = *(const ulonglong2*)wp;               // cols 8tx..+3
                ulonglong2 bB = *(const ulonglong2*)(wp + NOUT / 2);  // cols +4..+7
                #pragma unroll
                for (int j = 0; j < RPT; j++) {
                    u64 a2 = splat2(a_[j][dk]);
                    ffma2(acc[j][0], a2, bA.x);
                    ffma2(acc[j][1], a2, bA.y);
                    ffma2(acc[j][2], a2, bB.x);
                    ffma2(acc[j][3], a2, bB.y);
                }
            }
        }
    }

    // Epilogue: write h (fp16), and reduce al_s/al_d per (row, head) via shfl.
    #pragma unroll
    for (int j = 0; j < RPT; j++) {
        float c[8];
        #pragma unroll
        for (int i = 0; i < 4; i++) {
            float2 f = unpack2(acc[j][i]);
            c[2 * i] = f.x; c[2 * i + 1] = f.y;
        }
        float ss = 0.f, sd = 0.f;
        #pragma unroll
        for (int i = 0; i < 8; i++) {
            ss = fmaf(c[i], as_[tx * 8 + i], ss);
            sd = fmaf(c[i], ad_[tx * 8 + i], sd);
        }
        #pragma unroll
        for (int o = 4; o > 0; o >>= 1) {
            ss += __shfl_xor_sync(0xffffffffu, ss, o);
            sd += __shfl_xor_sync(0xffffffffu, sd, o);
        }
        int n = n0 + ty + TY * j;
        if (n < NNODE) {
            if ((tx & 7) == 0) {
                int head = (TX == 16) ? (tx >> 3) : 0;
                g_als[n * H + head] = ss;
                g_ald[n * H + head] = sd;
            }
            __half2 p0 = __floats2half2_rn(c[0], c[1]);
            __half2 p1 = __floats2half2_rn(c[2], c[3]);
            __half2 p2 = __floats2half2_rn(c[4], c[5]);
            __half2 p3 = __floats2half2_rn(c[6], c[7]);
            uint4 pk = make_uint4(
                *(unsigned int*)&p0, *(unsigned int*)&p1,
                *(unsigned int*)&p2, *(unsigned int*)&p3);
            *(uint4*)&g_h[(size_t)n * NOUT + tx * 8] = pk;
        }
    }
}

// ---------------- fused per-dst softmax + aggregation ------------------------
// Warp per node; alpha pass processes TWO edges per iteration (one per 16-lane
// half-warp: 16 lanes x 16B = one 256B fp16 row). Halves the serial loop depth
// and doubles MLP vs one-edge-per-iteration.
// g_ptr is inclusive-end after scatter: range = [ptr[d-1], ptr[d]), ptr[-1]=0.
__global__ __launch_bounds__(256) void agg128(const __half* __restrict__ hsrc,
                                              float* __restrict__ out) {
    int d    = (blockIdx.x * 256 + threadIdx.x) >> 5;
    int lane = threadIdx.x & 31;
    if (d >= NNODE) return;
    int p1 = g_ptr[d];
    int p0 = (d == 0) ? 0 : g_ptr[d - 1];
    float2 ad = ((const float2*)g_ald)[d];

    // z-pass (strided; ~1 iteration at avg degree)
    float z0 = 0.f, z1 = 0.f;
    for (int p = p0 + lane; p < p1; p += 32) {
        int s = g_ssrc[p];
        float2 as = ((const float2*)g_als)[s];
        float e0 = as.x + ad.x; e0 = e0 > 0.f ? e0 : 0.2f * e0;
        float e1 = as.y + ad.y; e1 = e1 > 0.f ? e1 : 0.2f * e1;
        z0 += __expf(e0); z1 += __expf(e1);
    }
    #pragma unroll
    for (int o = 16; o; o >>= 1) {
        z0 += __shfl_xor_sync(0xffffffffu, z0, o);
        z1 += __shfl_xor_sync(0xffffffffu, z1, o);
    }

    const int half    = lane >> 4;          // which edge of the pair
    const int sub     = lane & 15;          // 8 cols per lane
    const int head    = sub >> 3;           // cols 0-63 head0, 64-127 head1
    const float rz    = __fdividef(1.f, head ? z1 : z0);
    const float adh   = head ? ad.y : ad.x;

    float acc[8];
    #pragma unroll
    for (int i = 0; i < 8; i++) acc[i] = 0.f;

    int pe = p0 + half;
    int s = g_ssrc[pe < p1 ? pe : p1 - 1];
    for (int p = p0; p < p1; p += 2) {
        int pn = p + 2 + half;
        int sn = g_ssrc[pn < p1 ? pn : p1 - 1];
        float2 as = ((const float2*)g_als)[s];
        float e = (head ? as.y : as.x) + adh;
        e = e > 0.f ? e : 0.2f * e;
        float alpha = (p + half < p1) ? __expf(e) * rz : 0.f;
        uint4 hv = *(const uint4*)(hsrc + (size_t)s * 128 + sub * 8);
        float2 f0 = __half22float2(*(const __half2*)&hv.x);
        float2 f1 = __half22float2(*(const __half2*)&hv.y);
        float2 f2 = __half22float2(*(const __half2*)&hv.z);
        float2 f3 = __half22float2(*(const __half2*)&hv.w);
        acc[0] = fmaf(alpha, f0.x, acc[0]);
        acc[1] = fmaf(alpha, f0.y, acc[1]);
        acc[2] = fmaf(alpha, f1.x, acc[2]);
        acc[3] = fmaf(alpha, f1.y, acc[3]);
        acc[4] = fmaf(alpha, f2.x, acc[4]);
        acc[5] = fmaf(alpha, f2.y, acc[5]);
        acc[6] = fmaf(alpha, f3.x, acc[6]);
        acc[7] = fmaf(alpha, f3.y, acc[7]);
        s = sn;
    }
    // merge the two half-warps, lanes 0-15 write the row
    #pragma unroll
    for (int i = 0; i < 8; i++)
        acc[i] += __shfl_xor_sync(0xffffffffu, acc[i], 16);
    if (half == 0) {
        float4* op = (float4*)(out + (size_t)d * 128 + sub * 8);
        op[0] = make_float4(acc[0], acc[1], acc[2], acc[3]);
        op[1] = make_float4(acc[4], acc[5], acc[6], acc[7]);
    }
}

__global__ __launch_bounds__(256) void agg64(const __half* __restrict__ hsrc,
                                             float* __restrict__ out,
                                             const float* __restrict__ b3) {
    int d    = (blockIdx.x * 256 + threadIdx.x) >> 5;
    int lane = threadIdx.x & 31;
    if (d >= NNODE) return;
    int p1 = g_ptr[d];
    int p0 = (d == 0) ? 0 : g_ptr[d - 1];
    float adv = g_ald[d];
    float z = 0.f;
    for (int p = p0 + lane; p < p1; p += 32) {
        int s = g_ssrc[p];
        float e = g_als[s] + adv;
        e = e > 0.f ? e : 0.2f * e;
        z += __expf(e);
    }
    #pragma unroll
    for (int o = 16; o; o >>= 1) z += __shfl_xor_sync(0xffffffffu, z, o);
    float rz = __fdividef(1.f, z);

    const int half = lane >> 4;
    const int sub  = lane & 15;          // 4 cols per lane (16 lanes x 8B = 128B)

    float acc[4];
    #pragma unroll
    for (int i = 0; i < 4; i++) acc[i] = 0.f;

    int pe = p0 + half;
    int s = g_ssrc[pe < p1 ? pe : p1 - 1];
    for (int p = p0; p < p1; p += 2) {
        int pn = p + 2 + half;
        int sn = g_ssrc[pn < p1 ? pn : p1 - 1];
        float e = g_als[s] + adv;
        e = e > 0.f ? e : 0.2f * e;
        float alpha = (p + half < p1) ? __expf(e) * rz : 0.f;
        uint2 hv = *(const uint2*)(hsrc + (size_t)s * 64 + sub * 4);
        float2 f0 = __half22float2(*(const __half2*)&hv.x);
        float2 f1 = __half22float2(*(const __half2*)&hv.y);
        acc[0] = fmaf(alpha, f0.x, acc[0]);
        acc[1] = fmaf(alpha, f0.y, acc[1]);
        acc[2] = fmaf(alpha, f1.x, acc[2]);
        acc[3] = fmaf(alpha, f1.y, acc[3]);
        s = sn;
    }
    #pragma unroll
    for (int i = 0; i < 4; i++)
        acc[i] += __shfl_xor_sync(0xffffffffu, acc[i], 16);
    if (half == 0) {
        float4 bv = ((const float4*)b3)[sub];
        ((float4*)(out + (size_t)d * 64))[sub] =
            make_float4(acc[0] + bv.x, acc[1] + bv.y, acc[2] + bv.z, acc[3] + bv.w);
    }
}

// ---------------- launcher --------------------------------------------------
extern "C" void kernel_launch(void* const* d_in, const int* in_sizes, int n_in,
                              void* d_out, int out_size)
{
    const float* x   = (const float*)d_in[0];
    const int*   ei  = (const int*)d_in[1];     // int32: JAX x64 disabled
    const float* W1  = (const float*)d_in[2];
    const float* as1 = (const float*)d_in[3];
    const float* ad1 = (const float*)d_in[4];
    const float* b1  = (const float*)d_in[5];
    const float* W2  = (const float*)d_in[6];
    const float* as2 = (const float*)d_in[7];
    const float* ad2 = (const float*)d_in[8];
    const float* b2  = (const float*)d_in[9];
    const float* W3  = (const float*)d_in[10];
    const float* as3 = (const float*)d_in[11];
    const float* ad3 = (const float*)d_in[12];
    const float* b3  = (const float*)d_in[13];
    float* out = (float*)d_out;

    float* o_p; __half* h_p;
    cudaGetSymbolAddress((void**)&o_p, g_o);
    cudaGetSymbolAddress((void**)&h_p, g_h);

    const int SM128 = (BM * XSTR + KC * 128 + 2 * 128 + 128) * 4;  // 69120
    const int SM64  = (BM * XSTR + KC * 64  + 2 * 64  + 128) * 4;  // 52224
    cudaFuncSetAttribute(gemm_al<128, false>, cudaFuncAttributeMaxDynamicSharedMemorySize, SM128);
    cudaFuncSetAttribute(gemm_al<128, true >, cudaFuncAttributeMaxDynamicSharedMemorySize, SM128);
    cudaFuncSetAttribute(gemm_al<64,  true >, cudaFuncAttributeMaxDynamicSharedMemorySize, SM64);

    const int GB = (NNODE + BM - 1) / BM;       // 782
    const int EB = (ETOT + 255) / 256;
    const int AB = NNODE / 8;                   // 12500, warp per node
    const int SB = (NNODE + 255) / 256;         // scan23 blocks

    // ---- CSR build + layer-1 GEMM, ordered so launch #4 (= ncu capture slot)
    //      is gemm_al<128,false>. gemm1 is independent of the CSR kernels.
    hist_kernel<<<EB, 256>>>(ei);                       // 1
    scan1_kernel<<<NBLK, 256>>>();                      // 2 (also re-zeroes g_cnt)
    scan23_kernel<<<SB, 256>>>();                       // 3
    gemm_al<128, false><<<GB, 256, SM128>>>(x, W1, as1, ad1, nullptr);  // 4 <- ncu
    scatter_kernel<<<EB, 256>>>(ei);                    // 5 (g_ptr -> inclusive end)

    agg128<<<AB, 256>>>(h_p, o_p);                      // 6

    // ---- layer 2: relu(o1+b1) -> h2 (H=2 concat) ----
    gemm_al<128, true><<<GB, 256, SM128>>>(o_p, W2, as2, ad2, b1);
    agg128<<<AB, 256>>>(h_p, o_p);

    // ---- layer 3: relu(o2+b2) -> h3 (H=1, mean == identity), + b3 ----
    gemm_al<64, true><<<GB, 256, SM64>>>(o_p, W3, as3, ad3, b2);
    agg64<<<AB, 256>>>(h_p, out, b3);
}

// round 16
// speedup vs baseline: 1.5564x; 1.5564x over previous
#include <cuda_runtime.h>
#include <cuda_fp16.h>
#include <cstdint>
#include <type_traits>

#define NNODE 100000
#define NEDGE 1600000
#define ETOT  1700000   // NEDGE + NNODE self loops
#define NBLK  98        // ceil(NNODE / 1024) for the scan
#define BM    128       // rows per GEMM CTA
#define KC    64        // K chunk (2 chunks of 64)
#define XSTR  68        // xs chunk row stride (floats): 16B-aligned, bank+4/row

// ---------------- scratch (device globals; no allocation allowed) ----------
__device__ __half g_h [NNODE * 128];   // fp16 projected features (agg gather)
__device__ __half g_o [NNODE * 128];   // fp16 layer outputs (gemm input)
__device__ float g_als[NNODE * 2];
__device__ float g_ald[NNODE * 2];
__device__ int   g_cnt [NNODE];        // statically zero; re-zeroed by scan1
__device__ int   g_ptr [NNODE + 1];
__device__ int   g_bsum[128];
__device__ int   g_ssrc[ETOT];

// ---------------- f32x2 packed-FMA helpers (sm_103a) ------------------------
typedef unsigned long long u64;
__device__ __forceinline__ u64 splat2(float v) {
    u64 r; asm("mov.b64 %0, {%1, %1};" : "=l"(r) : "f"(v)); return r;
}
__device__ __forceinline__ void ffma2(u64& d, u64 a, u64 b) {
    asm("fma.rn.f32x2 %0, %1, %2, %0;" : "+l"(d) : "l"(a), "l"(b));
}
__device__ __forceinline__ float2 unpack2(u64 v) {
    float2 f; asm("mov.b64 {%0, %1}, %2;" : "=f"(f.x), "=f"(f.y) : "l"(v)); return f;
}

// ---------------- CSR build: hist -> scan -> scatter ------------------------
__global__ void hist_kernel(const int* __restrict__ ei) {
    int i = blockIdx.x * blockDim.x + threadIdx.x;
    if (i >= ETOT) return;
    int d = (i < NEDGE) ? ei[NEDGE + i] : (i - NEDGE);
    atomicAdd(&g_cnt[d], 1);
}

// Reads g_cnt, writes per-block-exclusive offsets into g_ptr, block totals to
// g_bsum, and ZEROES g_cnt for the next graph replay (launch is idempotent).
__global__ __launch_bounds__(256) void scan1_kernel() {
    __shared__ int warp_tot[8];
    __shared__ int wofs[8];
    int b = blockIdx.x, t = threadIdx.x;
    int gi = b * 1024 + t * 4;
    int c0 = (gi     < NNODE) ? g_cnt[gi]     : 0;
    int c1 = (gi + 1 < NNODE) ? g_cnt[gi + 1] : 0;
    int c2 = (gi + 2 < NNODE) ? g_cnt[gi + 2] : 0;
    int c3 = (gi + 3 < NNODE) ? g_cnt[gi + 3] : 0;
    if (gi     < NNODE) g_cnt[gi]     = 0;
    if (gi + 1 < NNODE) g_cnt[gi + 1] = 0;
    if (gi + 2 < NNODE) g_cnt[gi + 2] = 0;
    if (gi + 3 < NNODE) g_cnt[gi + 3] = 0;
    int ts = c0 + c1 + c2 + c3;
    int lane = t & 31, wid = t >> 5;
    int inc = ts;
    #pragma unroll
    for (int o = 1; o < 32; o <<= 1) {
        int v = __shfl_up_sync(0xffffffffu, inc, o);
        if (lane >= o) inc += v;
    }
    if (lane == 31) warp_tot[wid] = inc;
    __syncthreads();
    if (t == 0) {
        int acc = 0;
        #pragma unroll
        for (int w = 0; w < 8; w++) { wofs[w] = acc; acc += warp_tot[w]; }
        g_bsum[b] = acc;
    }
    __syncthreads();
    int base = wofs[wid] + inc - ts;
    if (gi     < NNODE) g_ptr[gi]     = base;
    if (gi + 1 < NNODE) g_ptr[gi + 1] = base + c0;
    if (gi + 2 < NNODE) g_ptr[gi + 2] = base + c0 + c1;
    if (gi + 3 < NNODE) g_ptr[gi + 3] = base + c0 + c1 + c2;
}

// Fused scan2+scan3: every block redoes the tiny 128-wide scan of g_bsum in
// smem (7 rounds), then adds its chunk's exclusive prefix to g_ptr.
__global__ __launch_bounds__(256) void scan23_kernel() {
    __shared__ int s[128];
    int t = threadIdx.x;
    if (t < 128) s[t] = (t < NBLK) ? g_bsum[t] : 0;
    __syncthreads();
    #pragma unroll
    for (int o = 1; o < 128; o <<= 1) {
        int u = 0;
        if (t < 128 && t >= o) u = s[t - o];
        __syncthreads();
        if (t < 128) s[t] += u;
        __syncthreads();
    }
    int i = blockIdx.x * 256 + t;
    int bidx = blockIdx.x >> 2;                  // 4 blocks per 1024-chunk
    int add = (bidx == 0) ? 0 : s[bidx - 1];     // exclusive chunk prefix
    if (i < NNODE) g_ptr[i] += add;
}

// scatter mutates g_ptr: atomicAdd turns exclusive start into inclusive end.
// After this kernel: g_ptr[d] = end(d); agg reads [ptr[d-1], ptr[d]), ptr[-1]=0.
// Replay-safe: scan1 rewrites g_ptr from scratch every launch.
__global__ void scatter_kernel(const int* __restrict__ ei) {
    int i = blockIdx.x * blockDim.x + threadIdx.x;
    if (i >= ETOT) return;
    int s, d;
    if (i < NEDGE) { s = ei[i]; d = ei[NEDGE + i]; }
    else           { s = d = i - NEDGE; }
    int pos = atomicAdd(&g_ptr[d], 1);
    g_ssrc[pos] = s;
}

// ---------------- fused GEMM + attention-logit epilogue (FFMA2) -------------
// h = act(X) @ W  (act = relu(x + bias) if TRANS), writes g_h (fp16), g_als,
// g_ald (fp32, from fp32 accumulators). TIN = float (layer 1 input) or __half
// (fp16 activations). BM=128, 8x8 thread tile, K chunked 2x64 (~69KB smem ->
// 2 CTAs/SM). FMA pipe is the binder.
template <int NOUT, bool TRANS, typename TIN>
__global__ __launch_bounds__(256, 2) void gemm_al(
    const TIN* __restrict__ X, const float* __restrict__ W,
    const float* __restrict__ asrc, const float* __restrict__ adst,
    const float* __restrict__ bias)
{
    constexpr int H   = NOUT / 64;
    constexpr int TX  = NOUT / 8;    // 16 (NOUT=128) or 8 (NOUT=64)
    constexpr int TY  = 256 / TX;    // 16 or 32
    constexpr int RPT = BM / TY;     // 8 or 4 rows per thread

    extern __shared__ float sm[];
    float* xs  = sm;                    // BM x XSTR (one 64-k chunk)
    float* ws  = sm + BM * XSTR;        // KC x NOUT (half-interleaved chunk)
    float* as_ = ws + KC * NOUT;        // NOUT
    float* ad_ = as_ + NOUT;            // NOUT
    float* bs  = ad_ + NOUT;            // 128

    const int tid = threadIdx.x;
    if (tid < NOUT) { as_[tid] = asrc[tid]; ad_[tid] = adst[tid]; }
    if (TRANS && tid < 128) bs[tid] = bias[tid];

    const int n0 = blockIdx.x * BM;
    const int ty = tid / TX, tx = tid % TX;

    u64 acc[RPT][4];
    #pragma unroll
    for (int j = 0; j < RPT; j++)
        #pragma unroll
        for (int i = 0; i < 4; i++) acc[j][i] = 0ull;

    const float4* W4  = (const float4*)W;
    float4*       ws4 = (float4*)ws;

    #pragma unroll
    for (int c = 0; c < 128 / KC; c++) {
        __syncthreads();   // protect smem reuse across chunks (and meta on c=0)

        // W chunk -> smem, half-interleaved within each k row
        #pragma unroll
        for (int i = tid; i < KC * NOUT / 4; i += 256) {
            int kk = i / (NOUT / 4);
            int c4 = i % (NOUT / 4);
            ws4[kk * (NOUT / 4) + (c4 & 1) * (NOUT / 8) + (c4 >> 1)] =
                W4[(size_t)(c * KC + kk) * (NOUT / 4) + c4];
        }

        // X chunk -> smem with fused relu(x + b); TIN-specific 4-wide load
        #pragma unroll
        for (int i = tid; i < BM * (KC / 4); i += 256) {
            int r   = i >> 4;              // KC/4 = 16
            int k4c = i & 15;
            int k4  = c * (KC / 4) + k4c;
            int n   = n0 + r;
            float4 v = make_float4(0.f, 0.f, 0.f, 0.f);
            if (n < NNODE) {
                if constexpr (std::is_same<TIN, float>::value) {
                    v = ((const float4*)X)[(size_t)n * 32 + k4];
                } else {
                    uint2 hv = ((const uint2*)X)[(size_t)n * 32 + k4];
                    float2 f01 = __half22float2(*(const __half2*)&hv.x);
                    float2 f23 = __half22float2(*(const __half2*)&hv.y);
                    v = make_float4(f01.x, f01.y, f23.x, f23.y);
                }
                if (TRANS) {
                    v.x = fmaxf(v.x + bs[k4 * 4 + 0], 0.f);
                    v.y = fmaxf(v.y + bs[k4 * 4 + 1], 0.f);
                    v.z = fmaxf(v.z + bs[k4 * 4 + 2], 0.f);
                    v.w = fmaxf(v.w + bs[k4 * 4 + 3], 0.f);
                }
            }
            *(float4*)(xs + r * XSTR + k4c * 4) = v;
        }
        __syncthreads();

        #pragma unroll 2
        for (int k0 = 0; k0 < KC; k0 += 4) {
            float a_[RPT][4];
            #pragma unroll
            for (int j = 0; j < RPT; j++) {
                float4 t = *(const float4*)(xs + (ty + TY * j) * XSTR + k0);
                a_[j][0] = t.x; a_[j][1] = t.y; a_[j][2] = t.z; a_[j][3] = t.w;
            }
            #pragma unroll
            for (int dk = 0; dk < 4; dk++) {
                const float* wp = ws + (k0 + dk) * NOUT + tx * 4;
                ulonglong2 bA = *(const ulonglong2*)wp;               // cols 8tx..+3
                ulonglong2 bB = *(const ulonglong2*)(wp + NOUT / 2);  // cols +4..+7
                #pragma unroll
                for (int j = 0; j < RPT; j++) {
                    u64 a2 = splat2(a_[j][dk]);
                    ffma2(acc[j][0], a2, bA.x);
                    ffma2(acc[j][1], a2, bA.y);
                    ffma2(acc[j][2], a2, bB.x);
                    ffma2(acc[j][3], a2, bB.y);
                }
            }
        }
    }

    // Epilogue: write h (fp16), and reduce al_s/al_d per (row, head) via shfl.
    #pragma unroll
    for (int j = 0; j < RPT; j++) {
        float c[8];
        #pragma unroll
        for (int i = 0; i < 4; i++) {
            float2 f = unpack2(acc[j][i]);
            c[2 * i] = f.x; c[2 * i + 1] = f.y;
        }
        float ss = 0.f, sd = 0.f;
        #pragma unroll
        for (int i = 0; i < 8; i++) {
            ss = fmaf(c[i], as_[tx * 8 + i], ss);
            sd = fmaf(c[i], ad_[tx * 8 + i], sd);
        }
        #pragma unroll
        for (int o = 4; o > 0; o >>= 1) {
            ss += __shfl_xor_sync(0xffffffffu, ss, o);
            sd += __shfl_xor_sync(0xffffffffu, sd, o);
        }
        int n = n0 + ty + TY * j;
        if (n < NNODE) {
            if ((tx & 7) == 0) {
                int head = (TX == 16) ? (tx >> 3) : 0;
                g_als[n * H + head] = ss;
                g_ald[n * H + head] = sd;
            }
            __half2 p0 = __floats2half2_rn(c[0], c[1]);
            __half2 p1 = __floats2half2_rn(c[2], c[3]);
            __half2 p2 = __floats2half2_rn(c[4], c[5]);
            __half2 p3 = __floats2half2_rn(c[6], c[7]);
            uint4 pk = make_uint4(
                *(unsigned int*)&p0, *(unsigned int*)&p1,
                *(unsigned int*)&p2, *(unsigned int*)&p3);
            *(uint4*)&g_h[(size_t)n * NOUT + tx * 8] = pk;
        }
    }
}

// ---------------- fused per-dst softmax + aggregation ------------------------
// Warp per node; alpha pass processes TWO edges per iteration (one per 16-lane
// half-warp: 16 lanes x 16B = one 256B fp16 row). Output stored fp16 (g_o).
// g_ptr is inclusive-end after scatter: range = [ptr[d-1], ptr[d]), ptr[-1]=0.
__global__ __launch_bounds__(256) void agg128(const __half* __restrict__ hsrc,
                                              __half* __restrict__ out) {
    int d    = (blockIdx.x * 256 + threadIdx.x) >> 5;
    int lane = threadIdx.x & 31;
    if (d >= NNODE) return;
    int p1 = g_ptr[d];
    int p0 = (d == 0) ? 0 : g_ptr[d - 1];
    float2 ad = ((const float2*)g_ald)[d];

    // z-pass (strided; ~1 iteration at avg degree)
    float z0 = 0.f, z1 = 0.f;
    for (int p = p0 + lane; p < p1; p += 32) {
        int s = g_ssrc[p];
        float2 as = ((const float2*)g_als)[s];
        float e0 = as.x + ad.x; e0 = e0 > 0.f ? e0 : 0.2f * e0;
        float e1 = as.y + ad.y; e1 = e1 > 0.f ? e1 : 0.2f * e1;
        z0 += __expf(e0); z1 += __expf(e1);
    }
    #pragma unroll
    for (int o = 16; o; o >>= 1) {
        z0 += __shfl_xor_sync(0xffffffffu, z0, o);
        z1 += __shfl_xor_sync(0xffffffffu, z1, o);
    }

    const int half    = lane >> 4;          // which edge of the pair
    const int sub     = lane & 15;          // 8 cols per lane
    const int head    = sub >> 3;           // cols 0-63 head0, 64-127 head1
    const float rz    = __fdividef(1.f, head ? z1 : z0);
    const float adh   = head ? ad.y : ad.x;

    float acc[8];
    #pragma unroll
    for (int i = 0; i < 8; i++) acc[i] = 0.f;

    int pe = p0 + half;
    int s = g_ssrc[pe < p1 ? pe : p1 - 1];
    for (int p = p0; p < p1; p += 2) {
        int pn = p + 2 + half;
        int sn = g_ssrc[pn < p1 ? pn : p1 - 1];
        float2 as = ((const float2*)g_als)[s];
        float e = (head ? as.y : as.x) + adh;
        e = e > 0.f ? e : 0.2f * e;
        float alpha = (p + half < p1) ? __expf(e) * rz : 0.f;
        uint4 hv = *(const uint4*)(hsrc + (size_t)s * 128 + sub * 8);
        float2 f0 = __half22float2(*(const __half2*)&hv.x);
        float2 f1 = __half22float2(*(const __half2*)&hv.y);
        float2 f2 = __half22float2(*(const __half2*)&hv.z);
        float2 f3 = __half22float2(*(const __half2*)&hv.w);
        acc[0] = fmaf(alpha, f0.x, acc[0]);
        acc[1] = fmaf(alpha, f0.y, acc[1]);
        acc[2] = fmaf(alpha, f1.x, acc[2]);
        acc[3] = fmaf(alpha, f1.y, acc[3]);
        acc[4] = fmaf(alpha, f2.x, acc[4]);
        acc[5] = fmaf(alpha, f2.y, acc[5]);
        acc[6] = fmaf(alpha, f3.x, acc[6]);
        acc[7] = fmaf(alpha, f3.y, acc[7]);
        s = sn;
    }
    // merge the two half-warps, lanes 0-15 write the row (fp16)
    #pragma unroll
    for (int i = 0; i < 8; i++)
        acc[i] += __shfl_xor_sync(0xffffffffu, acc[i], 16);
    if (half == 0) {
        __half2 q0 = __floats2half2_rn(acc[0], acc[1]);
        __half2 q1 = __floats2half2_rn(acc[2], acc[3]);
        __half2 q2 = __floats2half2_rn(acc[4], acc[5]);
        __half2 q3 = __floats2half2_rn(acc[6], acc[7]);
        uint4 pk = make_uint4(
            *(unsigned int*)&q0, *(unsigned int*)&q1,
            *(unsigned int*)&q2, *(unsigned int*)&q3);
        *(uint4*)(out + (size_t)d * 128 + sub * 8) = pk;
    }
}

__global__ __launch_bounds__(256) void agg64(const __half* __restrict__ hsrc,
                                             float* __restrict__ out,
                                             const float* __restrict__ b3) {
    int d    = (blockIdx.x * 256 + threadIdx.x) >> 5;
    int lane = threadIdx.x & 31;
    if (d >= NNODE) return;
    int p1 = g_ptr[d];
    int p0 = (d == 0) ? 0 : g_ptr[d - 1];
    float adv = g_ald[d];
    float z = 0.f;
    for (int p = p0 + lane; p < p1; p += 32) {
        int s = g_ssrc[p];
        float e = g_als[s] + adv;
        e = e > 0.f ? e : 0.2f * e;
        z += __expf(e);
    }
    #pragma unroll
    for (int o = 16; o; o >>= 1) z += __shfl_xor_sync(0xffffffffu, z, o);
    float rz = __fdividef(1.f, z);

    const int half = lane >> 4;
    const int sub  = lane & 15;          // 4 cols per lane (16 lanes x 8B = 128B)

    float acc[4];
    #pragma unroll
    for (int i = 0; i < 4; i++) acc[i] = 0.f;

    int pe = p0 + half;
    int s = g_ssrc[pe < p1 ? pe : p1 - 1];
    for (int p = p0; p < p1; p += 2) {
        int pn = p + 2 + half;
        int sn = g_ssrc[pn < p1 ? pn : p1 - 1];
        float e = g_als[s] + adv;
        e = e > 0.f ? e : 0.2f * e;
        float alpha = (p + half < p1) ? __expf(e) * rz : 0.f;
        uint2 hv = *(const uint2*)(hsrc + (size_t)s * 64 + sub * 4);
        float2 f0 = __half22float2(*(const __half2*)&hv.x);
        float2 f1 = __half22float2(*(const __half2*)&hv.y);
        acc[0] = fmaf(alpha, f0.x, acc[0]);
        acc[1] = fmaf(alpha, f0.y, acc[1]);
        acc[2] = fmaf(alpha, f1.x, acc[2]);
        acc[3] = fmaf(alpha, f1.y, acc[3]);
        s = sn;
    }
    #pragma unroll
    for (int i = 0; i < 4; i++)
        acc[i] += __shfl_xor_sync(0xffffffffu, acc[i], 16);
    if (half == 0) {
        float4 bv = ((const float4*)b3)[sub];
        ((float4*)(out + (size_t)d * 64))[sub] =
            make_float4(acc[0] + bv.x, acc[1] + bv.y, acc[2] + bv.z, acc[3] + bv.w);
    }
}

// ---------------- launcher --------------------------------------------------
extern "C" void kernel_launch(void* const* d_in, const int* in_sizes, int n_in,
                              void* d_out, int out_size)
{
    const float* x   = (const float*)d_in[0];
    const int*   ei  = (const int*)d_in[1];     // int32: JAX x64 disabled
    const float* W1  = (const float*)d_in[2];
    const float* as1 = (const float*)d_in[3];
    const float* ad1 = (const float*)d_in[4];
    const float* b1  = (const float*)d_in[5];
    const float* W2  = (const float*)d_in[6];
    const float* as2 = (const float*)d_in[7];
    const float* ad2 = (const float*)d_in[8];
    const float* b2  = (const float*)d_in[9];
    const float* W3  = (const float*)d_in[10];
    const float* as3 = (const float*)d_in[11];
    const float* ad3 = (const float*)d_in[12];
    const float* b3  = (const float*)d_in[13];
    float* out = (float*)d_out;

    __half *o_p, *h_p;
    cudaGetSymbolAddress((void**)&o_p, g_o);
    cudaGetSymbolAddress((void**)&h_p, g_h);

    const int SM128 = (BM * XSTR + KC * 128 + 2 * 128 + 128) * 4;  // 69120
    const int SM64  = (BM * XSTR + KC * 64  + 2 * 64  + 128) * 4;  // 52224
    cudaFuncSetAttribute(gemm_al<128, false, float >, cudaFuncAttributeMaxDynamicSharedMemorySize, SM128);
    cudaFuncSetAttribute(gemm_al<128, true,  __half>, cudaFuncAttributeMaxDynamicSharedMemorySize, SM128);
    cudaFuncSetAttribute(gemm_al<64,  true,  __half>, cudaFuncAttributeMaxDynamicSharedMemorySize, SM64);

    const int GB = (NNODE + BM - 1) / BM;       // 782
    const int EB = (ETOT + 255) / 256;
    const int AB = NNODE / 8;                   // 12500, warp per node
    const int SB = (NNODE + 255) / 256;         // scan23 blocks

    // ---- CSR build + layer-1 GEMM, ordered so launch #4 (= ncu capture slot)
    //      is gemm_al<128,false>. gemm1 is independent of the CSR kernels.
    hist_kernel<<<EB, 256>>>(ei);                       // 1
    scan1_kernel<<<NBLK, 256>>>();                      // 2 (also re-zeroes g_cnt)
    scan23_kernel<<<SB, 256>>>();                       // 3
    gemm_al<128, false, float><<<GB, 256, SM128>>>(x, W1, as1, ad1, nullptr);  // 4 <- ncu
    scatter_kernel<<<EB, 256>>>(ei);                    // 5 (g_ptr -> inclusive end)

    agg128<<<AB, 256>>>(h_p, o_p);                      // 6

    // ---- layer 2: relu(o1+b1) -> h2 (H=2 concat) ----
    gemm_al<128, true, __half><<<GB, 256, SM128>>>(o_p, W2, as2, ad2, b1);
    agg128<<<AB, 256>>>(h_p, o_p);

    // ---- layer 3: relu(o2+b2) -> h3 (H=1, mean == identity), + b3 ----
    gemm_al<64, true, __half><<<GB, 256, SM64>>>(o_p, W3, as3, ad3, b2);
    agg64<<<AB, 256>>>(h_p, out, b3);
}

// round 17
// speedup vs baseline: 1.5571x; 1.0005x over previous
#include <cuda_runtime.h>
#include <cuda_fp16.h>
#include <cstdint>
#include <type_traits>

#define NNODE 100000
#define NEDGE 1600000
#define ETOT  1700000   // NEDGE + NNODE self loops
#define NBLK  98        // ceil(NNODE / 1024) for the scan
#define BM    128       // rows per GEMM CTA
#define KC    64        // K chunk (2 chunks of 64)
#define XSTR  68        // xs chunk row stride (floats): 16B-aligned, bank+4/row

// ---------------- scratch (device globals; no allocation allowed) ----------
__device__ __half g_h [NNODE * 128];   // fp16 projected features (agg gather)
__device__ __half g_o [NNODE * 128];   // fp16 layer outputs (gemm input)
__device__ float g_als[NNODE * 2];
__device__ float g_ald[NNODE * 2];
__device__ int   g_cnt [NNODE];        // statically zero; re-zeroed by scan1
__device__ int   g_ptr [NNODE + 1];
__device__ int   g_bsum[128];
__device__ int   g_ssrc[ETOT];

// ---------------- f32x2 packed-FMA helpers (sm_103a) ------------------------
typedef unsigned long long u64;
__device__ __forceinline__ u64 splat2(float v) {
    u64 r; asm("mov.b64 %0, {%1, %1};" : "=l"(r) : "f"(v)); return r;
}
__device__ __forceinline__ void ffma2(u64& d, u64 a, u64 b) {
    asm("fma.rn.f32x2 %0, %1, %2, %0;" : "+l"(d) : "l"(a), "l"(b));
}
__device__ __forceinline__ float2 unpack2(u64 v) {
    float2 f; asm("mov.b64 {%0, %1}, %2;" : "=f"(f.x), "=f"(f.y) : "l"(v)); return f;
}

// ---------------- CSR build: hist -> scan -> scatter ------------------------
__global__ void hist_kernel(const int* __restrict__ ei) {
    int i = blockIdx.x * blockDim.x + threadIdx.x;
    if (i >= ETOT) return;
    int d = (i < NEDGE) ? ei[NEDGE + i] : (i - NEDGE);
    atomicAdd(&g_cnt[d], 1);
}

// Reads g_cnt, writes per-block-exclusive offsets into g_ptr, block totals to
// g_bsum, and ZEROES g_cnt for the next graph replay (launch is idempotent).
__global__ __launch_bounds__(256) void scan1_kernel() {
    __shared__ int warp_tot[8];
    __shared__ int wofs[8];
    int b = blockIdx.x, t = threadIdx.x;
    int gi = b * 1024 + t * 4;
    int c0 = (gi     < NNODE) ? g_cnt[gi]     : 0;
    int c1 = (gi + 1 < NNODE) ? g_cnt[gi + 1] : 0;
    int c2 = (gi + 2 < NNODE) ? g_cnt[gi + 2] : 0;
    int c3 = (gi + 3 < NNODE) ? g_cnt[gi + 3] : 0;
    if (gi     < NNODE) g_cnt[gi]     = 0;
    if (gi + 1 < NNODE) g_cnt[gi + 1] = 0;
    if (gi + 2 < NNODE) g_cnt[gi + 2] = 0;
    if (gi + 3 < NNODE) g_cnt[gi + 3] = 0;
    int ts = c0 + c1 + c2 + c3;
    int lane = t & 31, wid = t >> 5;
    int inc = ts;
    #pragma unroll
    for (int o = 1; o < 32; o <<= 1) {
        int v = __shfl_up_sync(0xffffffffu, inc, o);
        if (lane >= o) inc += v;
    }
    if (lane == 31) warp_tot[wid] = inc;
    __syncthreads();
    if (t == 0) {
        int acc = 0;
        #pragma unroll
        for (int w = 0; w < 8; w++) { wofs[w] = acc; acc += warp_tot[w]; }
        g_bsum[b] = acc;
    }
    __syncthreads();
    int base = wofs[wid] + inc - ts;
    if (gi     < NNODE) g_ptr[gi]     = base;
    if (gi + 1 < NNODE) g_ptr[gi + 1] = base + c0;
    if (gi + 2 < NNODE) g_ptr[gi + 2] = base + c0 + c1;
    if (gi + 3 < NNODE) g_ptr[gi + 3] = base + c0 + c1 + c2;
}

// Fused scan2+scan3: every block redoes the tiny 128-wide scan of g_bsum in
// smem (7 rounds), then adds its chunk's exclusive prefix to g_ptr.
__global__ __launch_bounds__(256) void scan23_kernel() {
    __shared__ int s[128];
    int t = threadIdx.x;
    if (t < 128) s[t] = (t < NBLK) ? g_bsum[t] : 0;
    __syncthreads();
    #pragma unroll
    for (int o = 1; o < 128; o <<= 1) {
        int u = 0;
        if (t < 128 && t >= o) u = s[t - o];
        __syncthreads();
        if (t < 128) s[t] += u;
        __syncthreads();
    }
    int i = blockIdx.x * 256 + t;
    int bidx = blockIdx.x >> 2;                  // 4 blocks per 1024-chunk
    int add = (bidx == 0) ? 0 : s[bidx - 1];     // exclusive chunk prefix
    if (i < NNODE) g_ptr[i] += add;
}

// scatter mutates g_ptr: atomicAdd turns exclusive start into inclusive end.
// After this kernel: g_ptr[d] = end(d); agg reads [ptr[d-1], ptr[d]), ptr[-1]=0.
// Replay-safe: scan1 rewrites g_ptr from scratch every launch.
__global__ void scatter_kernel(const int* __restrict__ ei) {
    int i = blockIdx.x * blockDim.x + threadIdx.x;
    if (i >= ETOT) return;
    int s, d;
    if (i < NEDGE) { s = ei[i]; d = ei[NEDGE + i]; }
    else           { s = d = i - NEDGE; }
    int pos = atomicAdd(&g_ptr[d], 1);
    g_ssrc[pos] = s;
}

// ---------------- fused GEMM + attention-logit epilogue (FFMA2) -------------
// h = act(X) @ W  (act = relu(x + bias) if TRANS), writes g_h (fp16), g_als,
// g_ald (fp32, from fp32 accumulators). TIN = float (layer 1 input) or __half
// (fp16 activations). BM=128, 8x8 thread tile, K chunked 2x64 (~69KB smem ->
// 2 CTAs/SM). FMA pipe is the binder.
template <int NOUT, bool TRANS, typename TIN>
__global__ __launch_bounds__(256, 2) void gemm_al(
    const TIN* __restrict__ X, const float* __restrict__ W,
    const float* __restrict__ asrc, const float* __restrict__ adst,
    const float* __restrict__ bias)
{
    constexpr int H   = NOUT / 64;
    constexpr int TX  = NOUT / 8;    // 16 (NOUT=128) or 8 (NOUT=64)
    constexpr int TY  = 256 / TX;    // 16 or 32
    constexpr int RPT = BM / TY;     // 8 or 4 rows per thread

    extern __shared__ float sm[];
    float* xs  = sm;                    // BM x XSTR (one 64-k chunk)
    float* ws  = sm + BM * XSTR;        // KC x NOUT (half-interleaved chunk)
    float* as_ = ws + KC * NOUT;        // NOUT
    float* ad_ = as_ + NOUT;            // NOUT
    float* bs  = ad_ + NOUT;            // 128

    const int tid = threadIdx.x;
    if (tid < NOUT) { as_[tid] = asrc[tid]; ad_[tid] = adst[tid]; }
    if (TRANS && tid < 128) bs[tid] = bias[tid];

    const int n0 = blockIdx.x * BM;
    const int ty = tid / TX, tx = tid % TX;

    u64 acc[RPT][4];
    #pragma unroll
    for (int j = 0; j < RPT; j++)
        #pragma unroll
        for (int i = 0; i < 4; i++) acc[j][i] = 0ull;

    const float4* W4  = (const float4*)W;
    float4*       ws4 = (float4*)ws;

    #pragma unroll
    for (int c = 0; c < 128 / KC; c++) {
        __syncthreads();   // protect smem reuse across chunks (and meta on c=0)

        // W chunk -> smem, half-interleaved within each k row
        #pragma unroll
        for (int i = tid; i < KC * NOUT / 4; i += 256) {
            int kk = i / (NOUT / 4);
            int c4 = i % (NOUT / 4);
            ws4[kk * (NOUT / 4) + (c4 & 1) * (NOUT / 8) + (c4 >> 1)] =
                W4[(size_t)(c * KC + kk) * (NOUT / 4) + c4];
        }

        // X chunk -> smem with fused relu(x + b); TIN-specific 4-wide load
        #pragma unroll
        for (int i = tid; i < BM * (KC / 4); i += 256) {
            int r   = i >> 4;              // KC/4 = 16
            int k4c = i & 15;
            int k4  = c * (KC / 4) + k4c;
            int n   = n0 + r;
            float4 v = make_float4(0.f, 0.f, 0.f, 0.f);
            if (n < NNODE) {
                if constexpr (std::is_same<TIN, float>::value) {
                    v = ((const float4*)X)[(size_t)n * 32 + k4];
                } else {
                    uint2 hv = ((const uint2*)X)[(size_t)n * 32 + k4];
                    float2 f01 = __half22float2(*(const __half2*)&hv.x);
                    float2 f23 = __half22float2(*(const __half2*)&hv.y);
                    v = make_float4(f01.x, f01.y, f23.x, f23.y);
                }
                if (TRANS) {
                    v.x = fmaxf(v.x + bs[k4 * 4 + 0], 0.f);
                    v.y = fmaxf(v.y + bs[k4 * 4 + 1], 0.f);
                    v.z = fmaxf(v.z + bs[k4 * 4 + 2], 0.f);
                    v.w = fmaxf(v.w + bs[k4 * 4 + 3], 0.f);
                }
            }
            *(float4*)(xs + r * XSTR + k4c * 4) = v;
        }
        __syncthreads();

        #pragma unroll 2
        for (int k0 = 0; k0 < KC; k0 += 4) {
            float a_[RPT][4];
            #pragma unroll
            for (int j = 0; j < RPT; j++) {
                float4 t = *(const float4*)(xs + (ty + TY * j) * XSTR + k0);
                a_[j][0] = t.x; a_[j][1] = t.y; a_[j][2] = t.z; a_[j][3] = t.w;
            }
            #pragma unroll
            for (int dk = 0; dk < 4; dk++) {
                const float* wp = ws + (k0 + dk) * NOUT + tx * 4;
                ulonglong2 bA = *(const ulonglong2*)wp;               // cols 8tx..+3
                ulonglong2 bB = *(const ulonglong2*)(wp + NOUT / 2);  // cols +4..+7
                #pragma unroll
                for (int j = 0; j < RPT; j++) {
                    u64 a2 = splat2(a_[j][dk]);
                    ffma2(acc[j][0], a2, bA.x);
                    ffma2(acc[j][1], a2, bA.y);
                    ffma2(acc[j][2], a2, bB.x);
                    ffma2(acc[j][3], a2, bB.y);
                }
            }
        }
    }

    // Epilogue: write h (fp16), and reduce al_s/al_d per (row, head) via shfl.
    #pragma unroll
    for (int j = 0; j < RPT; j++) {
        float c[8];
        #pragma unroll
        for (int i = 0; i < 4; i++) {
            float2 f = unpack2(acc[j][i]);
            c[2 * i] = f.x; c[2 * i + 1] = f.y;
        }
        float ss = 0.f, sd = 0.f;
        #pragma unroll
        for (int i = 0; i < 8; i++) {
            ss = fmaf(c[i], as_[tx * 8 + i], ss);
            sd = fmaf(c[i], ad_[tx * 8 + i], sd);
        }
        #pragma unroll
        for (int o = 4; o > 0; o >>= 1) {
            ss += __shfl_xor_sync(0xffffffffu, ss, o);
            sd += __shfl_xor_sync(0xffffffffu, sd, o);
        }
        int n = n0 + ty + TY * j;
        if (n < NNODE) {
            if ((tx & 7) == 0) {
                int head = (TX == 16) ? (tx >> 3) : 0;
                g_als[n * H + head] = ss;
                g_ald[n * H + head] = sd;
            }
            __half2 p0 = __floats2half2_rn(c[0], c[1]);
            __half2 p1 = __floats2half2_rn(c[2], c[3]);
            __half2 p2 = __floats2half2_rn(c[4], c[5]);
            __half2 p3 = __floats2half2_rn(c[6], c[7]);
            uint4 pk = make_uint4(
                *(unsigned int*)&p0, *(unsigned int*)&p1,
                *(unsigned int*)&p2, *(unsigned int*)&p3);
            *(uint4*)&g_h[(size_t)n * NOUT + tx * 8] = pk;
        }
    }
}

// ---------------- fused per-dst softmax + aggregation ------------------------
// Warp per node; alpha pass processes TWO edges per iteration (one per 16-lane
// half-warp: 16 lanes x 16B = one 256B fp16 row). Output stored fp16 (g_o).
// g_ptr is inclusive-end after scatter: range = [ptr[d-1], ptr[d]), ptr[-1]=0.
__global__ __launch_bounds__(256) void agg128(const __half* __restrict__ hsrc,
                                              __half* __restrict__ out) {
    int d    = (blockIdx.x * 256 + threadIdx.x) >> 5;
    int lane = threadIdx.x & 31;
    if (d >= NNODE) return;
    int p1 = g_ptr[d];
    int p0 = (d == 0) ? 0 : g_ptr[d - 1];
    float2 ad = ((const float2*)g_ald)[d];

    // z-pass (strided; ~1 iteration at avg degree)
    float z0 = 0.f, z1 = 0.f;
    for (int p = p0 + lane; p < p1; p += 32) {
        int s = g_ssrc[p];
        float2 as = ((const float2*)g_als)[s];
        float e0 = as.x + ad.x; e0 = e0 > 0.f ? e0 : 0.2f * e0;
        float e1 = as.y + ad.y; e1 = e1 > 0.f ? e1 : 0.2f * e1;
        z0 += __expf(e0); z1 += __expf(e1);
    }
    #pragma unroll
    for (int o = 16; o; o >>= 1) {
        z0 += __shfl_xor_sync(0xffffffffu, z0, o);
        z1 += __shfl_xor_sync(0xffffffffu, z1, o);
    }

    const int half    = lane >> 4;          // which edge of the pair
    const int sub     = lane & 15;          // 8 cols per lane
    const int head    = sub >> 3;           // cols 0-63 head0, 64-127 head1
    const float rz    = __fdividef(1.f, head ? z1 : z0);
    const float adh   = head ? ad.y : ad.x;

    float acc[8];
    #pragma unroll
    for (int i = 0; i < 8; i++) acc[i] = 0.f;

    int pe = p0 + half;
    int s = g_ssrc[pe < p1 ? pe : p1 - 1];
    for (int p = p0; p < p1; p += 2) {
        int pn = p + 2 + half;
        int sn = g_ssrc[pn < p1 ? pn : p1 - 1];
        float2 as = ((const float2*)g_als)[s];
        float e = (head ? as.y : as.x) + adh;
        e = e > 0.f ? e : 0.2f * e;
        float alpha = (p + half < p1) ? __expf(e) * rz : 0.f;
        uint4 hv = *(const uint4*)(hsrc + (size_t)s * 128 + sub * 8);
        float2 f0 = __half22float2(*(const __half2*)&hv.x);
        float2 f1 = __half22float2(*(const __half2*)&hv.y);
        float2 f2 = __half22float2(*(const __half2*)&hv.z);
        float2 f3 = __half22float2(*(const __half2*)&hv.w);
        acc[0] = fmaf(alpha, f0.x, acc[0]);
        acc[1] = fmaf(alpha, f0.y, acc[1]);
        acc[2] = fmaf(alpha, f1.x, acc[2]);
        acc[3] = fmaf(alpha, f1.y, acc[3]);
        acc[4] = fmaf(alpha, f2.x, acc[4]);
        acc[5] = fmaf(alpha, f2.y, acc[5]);
        acc[6] = fmaf(alpha, f3.x, acc[6]);
        acc[7] = fmaf(alpha, f3.y, acc[7]);
        s = sn;
    }
    // merge the two half-warps, lanes 0-15 write the row (fp16)
    #pragma unroll
    for (int i = 0; i < 8; i++)
        acc[i] += __shfl_xor_sync(0xffffffffu, acc[i], 16);
    if (half == 0) {
        __half2 q0 = __floats2half2_rn(acc[0], acc[1]);
        __half2 q1 = __floats2half2_rn(acc[2], acc[3]);
        __half2 q2 = __floats2half2_rn(acc[4], acc[5]);
        __half2 q3 = __floats2half2_rn(acc[6], acc[7]);
        uint4 pk = make_uint4(
            *(unsigned int*)&q0, *(unsigned int*)&q1,
            *(unsigned int*)&q2, *(unsigned int*)&q3);
        *(uint4*)(out + (size_t)d * 128 + sub * 8) = pk;
    }
}

__global__ __launch_bounds__(256) void agg64(const __half* __restrict__ hsrc,
                                             float* __restrict__ out,
                                             const float* __restrict__ b3) {
    int d    = (blockIdx.x * 256 + threadIdx.x) >> 5;
    int lane = threadIdx.x & 31;
    if (d >= NNODE) return;
    int p1 = g_ptr[d];
    int p0 = (d == 0) ? 0 : g_ptr[d - 1];
    float adv = g_ald[d];
    float z = 0.f;
    for (int p = p0 + lane; p < p1; p += 32) {
        int s = g_ssrc[p];
        float e = g_als[s] + adv;
        e = e > 0.f ? e : 0.2f * e;
        z += __expf(e);
    }
    #pragma unroll
    for (int o = 16; o; o >>= 1) z += __shfl_xor_sync(0xffffffffu, z, o);
    float rz = __fdividef(1.f, z);

    const int half = lane >> 4;
    const int sub  = lane & 15;          // 4 cols per lane (16 lanes x 8B = 128B)

    float acc[4];
    #pragma unroll
    for (int i = 0; i < 4; i++) acc[i] = 0.f;

    int pe = p0 + half;
    int s = g_ssrc[pe < p1 ? pe : p1 - 1];
    for (int p = p0; p < p1; p += 2) {
        int pn = p + 2 + half;
        int sn = g_ssrc[pn < p1 ? pn : p1 - 1];
        float e = g_als[s] + adv;
        e = e > 0.f ? e : 0.2f * e;
        float alpha = (p + half < p1) ? __expf(e) * rz : 0.f;
        uint2 hv = *(const uint2*)(hsrc + (size_t)s * 64 + sub * 4);
        float2 f0 = __half22float2(*(const __half2*)&hv.x);
        float2 f1 = __half22float2(*(const __half2*)&hv.y);
        acc[0] = fmaf(alpha, f0.x, acc[0]);
        acc[1] = fmaf(alpha, f0.y, acc[1]);
        acc[2] = fmaf(alpha, f1.x, acc[2]);
        acc[3] = fmaf(alpha, f1.y, acc[3]);
        s = sn;
    }
    #pragma unroll
    for (int i = 0; i < 4; i++)
        acc[i] += __shfl_xor_sync(0xffffffffu, acc[i], 16);
    if (half == 0) {
        float4 bv = ((const float4*)b3)[sub];
        ((float4*)(out + (size_t)d * 64))[sub] =
            make_float4(acc[0] + bv.x, acc[1] + bv.y, acc[2] + bv.z, acc[3] + bv.w);
    }
}

// ---------------- launcher --------------------------------------------------
extern "C" void kernel_launch(void* const* d_in, const int* in_sizes, int n_in,
                              void* d_out, int out_size)
{
    const float* x   = (const float*)d_in[0];
    const int*   ei  = (const int*)d_in[1];     // int32: JAX x64 disabled
    const float* W1  = (const float*)d_in[2];
    const float* as1 = (const float*)d_in[3];
    const float* ad1 = (const float*)d_in[4];
    const float* b1  = (const float*)d_in[5];
    const float* W2  = (const float*)d_in[6];
    const float* as2 = (const float*)d_in[7];
    const float* ad2 = (const float*)d_in[8];
    const float* b2  = (const float*)d_in[9];
    const float* W3  = (const float*)d_in[10];
    const float* as3 = (const float*)d_in[11];
    const float* ad3 = (const float*)d_in[12];
    const float* b3  = (const float*)d_in[13];
    float* out = (float*)d_out;

    __half *o_p, *h_p;
    cudaGetSymbolAddress((void**)&o_p, g_o);
    cudaGetSymbolAddress((void**)&h_p, g_h);

    const int SM128 = (BM * XSTR + KC * 128 + 2 * 128 + 128) * 4;  // 69120
    const int SM64  = (BM * XSTR + KC * 64  + 2 * 64  + 128) * 4;  // 52224
    cudaFuncSetAttribute(gemm_al<128, false, float >, cudaFuncAttributeMaxDynamicSharedMemorySize, SM128);
    cudaFuncSetAttribute(gemm_al<128, true,  __half>, cudaFuncAttributeMaxDynamicSharedMemorySize, SM128);
    cudaFuncSetAttribute(gemm_al<64,  true,  __half>, cudaFuncAttributeMaxDynamicSharedMemorySize, SM64);

    const int GB = (NNODE + BM - 1) / BM;       // 782
    const int EB = (ETOT + 255) / 256;
    const int AB = NNODE / 8;                   // 12500, warp per node
    const int SB = (NNODE + 255) / 256;         // scan23 blocks

    // ---- CSR build + layer-1 GEMM, ordered so launch #4 (= ncu capture slot)
    //      is gemm_al<128,false>. gemm1 is independent of the CSR kernels.
    hist_kernel<<<EB, 256>>>(ei);                       // 1
    scan1_kernel<<<NBLK, 256>>>();                      // 2 (also re-zeroes g_cnt)
    scan23_kernel<<<SB, 256>>>();                       // 3
    gemm_al<128, false, float><<<GB, 256, SM128>>>(x, W1, as1, ad1, nullptr);  // 4 <- ncu
    scatter_kernel<<<EB, 256>>>(ei);                    // 5 (g_ptr -> inclusive end)

    agg128<<<AB, 256>>>(h_p, o_p);                      // 6

    // ---- layer 2: relu(o1+b1) -> h2 (H=2 concat) ----
    gemm_al<128, true, __half><<<GB, 256, SM128>>>(o_p, W2, as2, ad2, b1);
    agg128<<<AB, 256>>>(h_p, o_p);

    // ---- layer 3: relu(o2+b2) -> h3 (H=1, mean == identity), + b3 ----
    gemm_al<64, true, __half><<<GB, 256, SM64>>>(o_p, W3, as3, ad3, b2);
    agg64<<<AB, 256>>>(h_p, out, b3);
}